// round 14
// baseline (speedup 1.0000x reference)
#include <cuda_runtime.h>
#include <cstdint>

__device__ __forceinline__ float wred(float v){
    #pragma unroll
    for (int o = 16; o; o >>= 1) v += __shfl_xor_sync(0xffffffffu, v, o);
    return v;
}

// packed f32x2 multiply: a.lo*=v.lo, a.hi*=v.hi  (sm_100 family)
__device__ __forceinline__ void mul2(unsigned long long& a, unsigned long long v){
    asm("mul.rn.f32x2 %0, %0, %1;" : "+l"(a) : "l"(v));
}
__device__ __forceinline__ void lds_v2u64(unsigned long long& lo, unsigned long long& hi, uint32_t addr){
    asm volatile("ld.shared.v2.u64 {%0,%1}, [%2];" : "=l"(lo), "=l"(hi) : "r"(addr));
}
__device__ __forceinline__ void unpackf2(float& x, float& y, unsigned long long v){
    asm("mov.b64 {%0,%1}, %2;" : "=f"(x), "=f"(y) : "l"(v));
}

__global__ void __launch_bounds__(256)
qie_kernel(const float* __restrict__ x,      // [8,16,4,3]
           const float* __restrict__ posw,   // [16,2]
           const float* __restrict__ l1w,    // [20,3]
           const float* __restrict__ l2w,    // [16,3]
           const float* __restrict__ hw,     // [512,4]
           const float* __restrict__ hb,     // [512]
           float* __restrict__ out)          // [8,512]
{
    // M layout: [qubit][sympl pauli][block], sympl index = x | z<<1:
    //   0=I (always 1), 1=X, 2=Z, 3=Y
    __shared__ __align__(16) float M[20][4][4];
    __shared__ float Nv[16][3];                   // Bloch rows of O_q (X,Y,Z order)
    __shared__ __align__(16) float accF[4][4];    // parts0-3 x warps0-2 (col 3 unused)
    __shared__ __align__(16) float accP[4];       // [e123, e01a, e01b, e012]
    __shared__ __align__(16) float gpart[15][128];// Gram per-thread partials
    __shared__ __align__(16) float gsh[16];       // [0..9]=G(i<=j),[10..13]=W^T b,[14]=b.b

    const int b = blockIdx.x;
    const int t = threadIdx.x;
    const int warp = t >> 5, lane = t & 31;

    // ---- warps 0..2 (threads 0..79): per-qubit Bloch vectors.
    //      warp 3 lanes 0..15: observable Bloch rows.
    //      warps 4..7: Gram partials (4 rows/thread, NO reductions pre-barrier).
    if (t < 80) {
        const int qb = t / 20, i = t % 20;
        const int p = 4*qb + i/5, j = i % 5;
        float A0, A1, A2;
        if (j < 4) {
            const float* xp = x + (((size_t)b*16 + p)*4 + j)*3;
            A0 = xp[0]; A1 = xp[1]; A2 = xp[2];
        } else {
            A0 = posw[2*p]; A1 = posw[2*p+1]; A2 = 0.f;   // rz(0)=I
        }
        const float B0 = l1w[3*i], B1 = l1w[3*i+1], B2 = l1w[3*i+2];
        float s0,c0,s1,c1,s2,c2, t0,d0,t1,d1,t2,d2;
        __sincosf(A0,&s0,&c0); __sincosf(A1,&s1,&c1); __sincosf(A2,&s2,&c2);
        __sincosf(B0,&t0,&d0); __sincosf(B1,&t1,&d1); __sincosf(B2,&t2,&d2);
        // v = Rz(A2)Ry(A1)Rx(A0) e_z
        float vx = s1*c0, vy = -s0, vz = c1*c0;
        float nx = c2*vx - s2*vy, ny = s2*vx + c2*vy; vx = nx; vy = ny;  // Rz(A2)
        ny = d0*vy - t0*vz;  vz = t0*vy + d0*vz;  vy = ny;               // Rx(B0)
        nx = d1*vx + t1*vz;  vz = -t1*vx + d1*vz; vx = nx;               // Ry(B1)
        nx = d2*vx - t2*vy;  ny = t2*vx + d2*vy;  vx = nx; vy = ny;      // Rz(B2)
        M[i][0][qb] = 1.f; M[i][1][qb] = vx; M[i][2][qb] = vz; M[i][3][qb] = vy;
    } else if (t >= 96 && t < 112) {
        const int q = t - 96;
        float sa, ca, sb, cb;
        __sincosf(l2w[3*q],   &sa, &ca);
        __sincosf(l2w[3*q+1], &sb, &cb);
        Nv[q][0] = -sb; Nv[q][1] = sa*cb; Nv[q][2] = ca*cb;
    } else if (t >= 128) {
        const int r0 = (t - 128) * 4;
        float g[15];
        #pragma unroll
        for (int k = 0; k < 15; ++k) g[k] = 0.f;
        #pragma unroll
        for (int r = 0; r < 4; ++r) {
            const float4 w = ((const float4*)hw)[r0 + r];
            const float bv = hb[r0 + r];
            g[0]+=w.x*w.x; g[1]+=w.x*w.y; g[2]+=w.x*w.z; g[3]+=w.x*w.w;
            g[4]+=w.y*w.y; g[5]+=w.y*w.z; g[6]+=w.y*w.w;
            g[7]+=w.z*w.z; g[8]+=w.z*w.w; g[9]+=w.w*w.w;
            g[10]+=w.x*bv; g[11]+=w.y*bv; g[12]+=w.z*bv; g[13]+=w.w*bv;
            g[14]+=bv*bv;
        }
        #pragma unroll
        for (int k = 0; k < 15; ++k) gpart[k][t - 128] = g[k];
    }

    // ---- prefetch per-thread head rows: PAIRED outputs 2t, 2t+1
    const int k0 = 2*t, k1 = 2*t + 1;
    const float4 w0 = ((const float4*)hw)[k0];
    const float4 w1 = ((const float4*)hw)[k1];
    const float b0 = hb[k0], b1 = hb[k1];

    // ---- compact pattern enumeration (144 useful patterns on warps 0..4)
    // role 0 (t<81):        full patterns, a_j in {1,2,3}          -> parts 0..3
    // role 1 (w3 l<27):     e123: a0=0, a1..a3 in {1,2,3}          -> accP[0]
    // role 2 (w3 l>=27 / w4 l>=27): e01: a0,a1 in {1,2,3}, a2=a3=0 -> accP[1]/[2]
    // role 3 (w4 l<27):     e012: a3=0, a0..a2 in {1,2,3}          -> accP[3]
    int a0=0, a1=0, a2=0, a3=0, role = -1;
    if (t < 81) {
        role = 0; int f = t;
        a0 = f%3 + 1; f /= 3; a1 = f%3 + 1; f /= 3; a2 = f%3 + 1; a3 = f/3 + 1;
    } else if (t >= 96 && t < 128) {
        const int l = t - 96;
        if (l < 27) { role = 1; int f = l; a1 = f%3+1; f /= 3; a2 = f%3+1; a3 = f/3+1; }
        else        { role = 2; int f = l - 27; a0 = f%3+1; a1 = f/3+1; }       // f 0..4
    } else if (t >= 128 && t < 159) {
        const int l = t - 128;
        if (l < 27) { role = 3; int f = l; a0 = f%3+1; f /= 3; a1 = f%3+1; a2 = f/3+1; }
        else        { role = 2; int f = l - 22; a0 = f%3+1; a1 = f/3+1; }       // f 5..8
    }

    // ---- closed-form Clifford pullback through the 20-CNOT ring (pure ALU).
    const int x0 = (a0 ^ (a0 >> 1)) & 1, z0 = (a0 >> 1) & 1;
    const int x1 = (a1 ^ (a1 >> 1)) & 1, z1 = (a1 >> 1) & 1;
    const int x2 = (a2 ^ (a2 >> 1)) & 1, z2 = (a2 >> 1) & 1;
    const int x3 = (a3 ^ (a3 >> 1)) & 1, z3 = (a3 >> 1) & 1;
    const int p0 =  x0       | ((z1 ^ z2 ^ z3)      << 1);
    const int p1 = (x0 ^ x1) | ((z0 ^ z1 ^ z2 ^ z3) << 1);
    const int p2 = (x1 ^ x2) | ((z0 ^ z2 ^ z3)      << 1);
    const int p3 = (x2 ^ x3) | ((z0 ^ z3)           << 1);
    const int p4 =  x3       | ( z0                 << 1);
    const int S1 = z0 ^ z1 ^ z2 ^ z3, S2 = z0 ^ z2 ^ z3, S3 = z0 ^ z3, S4 = z0;
    const int sign = (x0 & S1 & (1 ^ x1 ^ z0)) ^ (x1 & S2 & (1 ^ x2 ^ z1))
                   ^ (x2 & S3 & (1 ^ x3 ^ z2)) ^ (x3 & S4 & (1 ^ z3));
    const float sgn = 1.f - 2.f * (float)sign;

    // ---- precompute ALL shared addresses BEFORE the barrier (threads are
    //      otherwise waiting; first LDS can issue at barrier release + 1).
    uint32_t ad[20];
    {
        const uint32_t mb = (uint32_t)__cvta_generic_to_shared(M);
        const int iz = z0 << 1;
        ad[0] = mb + (0*4 + p0)*16; ad[1] = mb + (1*4 + p1)*16;
        ad[2] = mb + (2*4 + p2)*16; ad[3] = mb + (3*4 + p3)*16;
        ad[4] = mb + (4*4 + p4)*16;
        #pragma unroll
        for (int i = 5; i < 20; ++i) ad[i] = mb + (i*4 + iz)*16;
    }
    const int i0 = a0 ? a0-1 : 0, i1 = a1 ? a1-1 : 0,
              i2 = a2 ? a2-1 : 0, i3 = a3 ? a3-1 : 0;

    __syncthreads();   // barrier 1: M, Nv, gpart ready

    if (warp < 5) {
        // ---- <psi_qb | P | psi_qb> (packed f32x2, even/odd split) — first
        float v0, v1, v2, v3;
        {
            unsigned long long aE01, aE23, aO01, aO23;
            lds_v2u64(aE01, aE23, ad[0]);
            lds_v2u64(aO01, aO23, ad[1]);
            #pragma unroll
            for (int i = 2; i < 20; i += 2) {
                unsigned long long lo, hi;
                lds_v2u64(lo, hi, ad[i]);
                mul2(aE01, lo); mul2(aE23, hi);
                lds_v2u64(lo, hi, ad[i+1]);
                mul2(aO01, lo); mul2(aO23, hi);
            }
            mul2(aE01, aO01); mul2(aE23, aO23);
            unpackf2(v0, v1, aE01);
            unpackf2(v2, v3, aE23);
            v0 *= sgn; v1 *= sgn; v2 *= sgn; v3 *= sgn;
        }

        // ---- observable factors (overlap with product chain above)
        const float m0 = a0 ? Nv[0][i0] : 1.f;
        const float m1 = a1 ? Nv[1][i1] : 1.f;
        const float m2 = a2 ? Nv[2][i2] : 1.f;
        const float m3 = a3 ? Nv[3][i3] : 1.f;
        const float nfA = (m0*m1) * (m2*m3);      // valid for roles 0..3
        float nf1 = 0.f, nf2 = 0.f, nf3 = 0.f;
        if (role == 0) {
            nf1 = (Nv[4][i0]*Nv[5][i1])   * (Nv[6][i2]*Nv[7][i3]);
            nf2 = (Nv[8][i0]*Nv[9][i1])   * (Nv[10][i2]*Nv[11][i3]);
            nf3 = (Nv[12][i0]*Nv[13][i1]) * (Nv[14][i2]*Nv[15][i3]);
        }

        if (warp < 3) {
            // full patterns: 4 wreds (inactive lanes t=81..95 contribute 0)
            const bool act = (t < 81);
            float r0 = wred(act ? nfA*v0 : 0.f);
            float r1 = wred(act ? nf1*v1 : 0.f);
            float r2 = wred(act ? nf2*v2 : 0.f);
            float r3 = wred(act ? nf3*v3 : 0.f);
            if (lane == 0) {
                accF[0][warp] = r0; accF[1][warp] = r1;
                accF[2][warp] = r2; accF[3][warp] = r3;
            }
        } else if (warp == 3) {
            float r4 = wred(role == 1 ? nfA*v0 : 0.f);   // e123
            float r5 = wred(role == 2 ? nfA*v0 : 0.f);   // e01 (first 5)
            if (lane == 0) { accP[0] = r4; accP[1] = r5; }
        } else { // warp == 4
            float r6 = wred(role == 3 ? nfA*v0 : 0.f);   // e012
            float r5 = wred(role == 2 ? nfA*v0 : 0.f);   // e01 (last 4)
            if (lane == 0) { accP[3] = r6; accP[2] = r5; }
        }
    } else {
        // ---- warps 5..7: Gram combine, 5 components each
        const int base = (warp - 5) * 5;
        #pragma unroll
        for (int c = 0; c < 5; ++c) {
            const int k = base + c;
            float4 p4v = *(const float4*)&gpart[k][lane*4];
            float s = (p4v.x + p4v.y) + (p4v.z + p4v.w);
            s = wred(s);
            if (lane == 0) gsh[k] = s;
        }
    }
    __syncthreads();   // barrier 2: accF, accP, gsh ready

    // ---- final combine (all threads, fixed order)
    const float E0 = (accF[0][0] + accF[0][1]) + accF[0][2];
    const float E1 = (accF[1][0] + accF[1][1]) + accF[1][2];
    const float E2 = (accF[2][0] + accF[2][1]) + accF[2][2];
    const float E3 = (accF[3][0] + accF[3][1]) + accF[3][2];
    const float4 ap = *(const float4*)&accP[0];
    const float q0 = ap.x * (E1*E2) * E3;     // e123 * Efull[1..3]
    const float q1 = ap.y + ap.z;             // e01
    const float q2 = ap.w;                    // e012
    const float q3 = E0;                      // Efull[0]

    // ---- head: y = q @ W^T + b ; norm via Gram (balanced tree, no fmax)
    const float y0 = b0 + q0*w0.x + q1*w0.y + q2*w0.z + q3*w0.w;
    const float y1 = b1 + q0*w1.x + q1*w1.y + q2*w1.z + q3*w1.w;

    // gsh: [0]=G00 [1]=G01 [2]=G02 [3]=G03 [4]=G11 [5]=G12 [6]=G13
    //      [7]=G22 [8]=G23 [9]=G33 [10]=c0 [11]=c1 [12]=c2 [13]=c3 [14]=bb
    const float nA = gsh[0]*q0*q0 + gsh[4]*q1*q1;
    const float nB = gsh[7]*q2*q2 + gsh[9]*q3*q3;
    const float nC = gsh[1]*q0*q1 + gsh[2]*q0*q2;
    const float nD = gsh[3]*q0*q3 + gsh[5]*q1*q2;
    const float nE = gsh[6]*q1*q3 + gsh[8]*q2*q3;
    const float nF = gsh[10]*q0 + gsh[11]*q1;
    const float nG = gsh[12]*q2 + gsh[13]*q3;
    const float n  = (gsh[14] + (nA + nB)) + 2.f*((nC + nD) + (nE + (nF + nG)));
    const float r = rsqrtf(n);     // n >= b.b > 0 for this head; guard vacuous
    ((float2*)(out + (size_t)b*512))[t] = make_float2(y0*r, y1*r);
}

extern "C" void kernel_launch(void* const* d_in, const int* in_sizes, int n_in,
                              void* d_out, int out_size)
{
    // Map inputs by unique element counts:
    // x=1536, pos_weights=32, layer_1_weights=60, layer_2_weights=48,
    // head_w=2048, head_b=512
    const float *x = nullptr, *pw = nullptr, *l1 = nullptr,
                *l2 = nullptr, *hw = nullptr, *hb = nullptr;
    for (int i = 0; i < n_in; ++i) {
        const float* p = (const float*)d_in[i];
        switch (in_sizes[i]) {
            case 1536: x  = p; break;
            case 32:   pw = p; break;
            case 60:   l1 = p; break;
            case 48:   l2 = p; break;
            case 2048: hw = p; break;
            case 512:  hb = p; break;
            default: break;
        }
    }
    qie_kernel<<<8, 256>>>(x, pw, l1, l2, hw, hb, (float*)d_out);
}

// round 15
// speedup vs baseline: 1.3420x; 1.3420x over previous
#include <cuda_runtime.h>
#include <cstdint>

__device__ __forceinline__ float wred(float v){
    #pragma unroll
    for (int o = 16; o; o >>= 1) v += __shfl_xor_sync(0xffffffffu, v, o);
    return v;
}

// packed f32x2 multiply: a.lo*=v.lo, a.hi*=v.hi  (sm_100 family)
__device__ __forceinline__ void mul2(unsigned long long& a, unsigned long long v){
    asm("mul.rn.f32x2 %0, %0, %1;" : "+l"(a) : "l"(v));
}
__device__ __forceinline__ void lds_v2u64(unsigned long long& lo, unsigned long long& hi, uint32_t addr){
    asm volatile("ld.shared.v2.u64 {%0,%1}, [%2];" : "=l"(lo), "=l"(hi) : "r"(addr));
}
__device__ __forceinline__ void unpackf2(float& x, float& y, unsigned long long v){
    asm("mov.b64 {%0,%1}, %2;" : "=f"(x), "=f"(y) : "l"(v));
}

__global__ void __launch_bounds__(256)
qie_kernel(const float* __restrict__ x,      // [8,16,4,3]
           const float* __restrict__ posw,   // [16,2]
           const float* __restrict__ l1w,    // [20,3]
           const float* __restrict__ l2w,    // [16,3]
           const float* __restrict__ hw,     // [512,4]
           const float* __restrict__ hb,     // [512]
           float* __restrict__ out)          // [8,512]
{
    // M layout: [qubit][sympl pauli][block], sympl index = x | z<<1:
    //   0=I (always 1), 1=X, 2=Z, 3=Y
    __shared__ __align__(16) float M[20][4][4];
    __shared__ float Nv[16][3];                   // Bloch rows of O_q (X,Y,Z order)
    __shared__ __align__(16) float accF[4][4];    // parts0-3 x warps0-2 (col 3 unused)
    __shared__ __align__(16) float accP[4];       // [e123, e01a, e01b, e012]
    __shared__ __align__(16) float gpart[15][128];// Gram per-thread partials
    __shared__ __align__(16) float gsh[16];       // [0..9]=G(i<=j),[10..13]=W^T b,[14]=b.b

    const int b = blockIdx.x;
    const int t = threadIdx.x;
    const int warp = t >> 5, lane = t & 31;

    // ---- warps 0..2 (threads 0..79): per-qubit Bloch vectors.
    //      warp 3 lanes 0..15: observable Bloch rows.
    //      warps 4..7: Gram partials (4 rows/thread, NO reductions pre-barrier).
    if (t < 80) {
        const int qb = t / 20, i = t % 20;
        const int p = 4*qb + i/5, j = i % 5;
        float A0, A1, A2;
        if (j < 4) {
            const float* xp = x + (((size_t)b*16 + p)*4 + j)*3;
            A0 = xp[0]; A1 = xp[1]; A2 = xp[2];
        } else {
            A0 = posw[2*p]; A1 = posw[2*p+1]; A2 = 0.f;   // rz(0)=I
        }
        const float B0 = l1w[3*i], B1 = l1w[3*i+1], B2 = l1w[3*i+2];
        float s0,c0,s1,c1,s2,c2, t0,d0,t1,d1,t2,d2;
        __sincosf(A0,&s0,&c0); __sincosf(A1,&s1,&c1); __sincosf(A2,&s2,&c2);
        __sincosf(B0,&t0,&d0); __sincosf(B1,&t1,&d1); __sincosf(B2,&t2,&d2);
        // v = Rz(A2)Ry(A1)Rx(A0) e_z
        float vx = s1*c0, vy = -s0, vz = c1*c0;
        float nx = c2*vx - s2*vy, ny = s2*vx + c2*vy; vx = nx; vy = ny;  // Rz(A2)
        ny = d0*vy - t0*vz;  vz = t0*vy + d0*vz;  vy = ny;               // Rx(B0)
        nx = d1*vx + t1*vz;  vz = -t1*vx + d1*vz; vx = nx;               // Ry(B1)
        nx = d2*vx - t2*vy;  ny = t2*vx + d2*vy;  vx = nx; vy = ny;      // Rz(B2)
        M[i][0][qb] = 1.f; M[i][1][qb] = vx; M[i][2][qb] = vz; M[i][3][qb] = vy;
    } else if (t >= 96 && t < 112) {
        const int q = t - 96;
        float sa, ca, sb, cb;
        __sincosf(l2w[3*q],   &sa, &ca);
        __sincosf(l2w[3*q+1], &sb, &cb);
        Nv[q][0] = -sb; Nv[q][1] = sa*cb; Nv[q][2] = ca*cb;
    } else if (t >= 128) {
        const int r0 = (t - 128) * 4;
        float g[15];
        #pragma unroll
        for (int k = 0; k < 15; ++k) g[k] = 0.f;
        #pragma unroll
        for (int r = 0; r < 4; ++r) {
            const float4 w = ((const float4*)hw)[r0 + r];
            const float bv = hb[r0 + r];
            g[0]+=w.x*w.x; g[1]+=w.x*w.y; g[2]+=w.x*w.z; g[3]+=w.x*w.w;
            g[4]+=w.y*w.y; g[5]+=w.y*w.z; g[6]+=w.y*w.w;
            g[7]+=w.z*w.z; g[8]+=w.z*w.w; g[9]+=w.w*w.w;
            g[10]+=w.x*bv; g[11]+=w.y*bv; g[12]+=w.z*bv; g[13]+=w.w*bv;
            g[14]+=bv*bv;
        }
        #pragma unroll
        for (int k = 0; k < 15; ++k) gpart[k][t - 128] = g[k];
    }

    // ---- prefetch per-thread head rows: PAIRED outputs 2t, 2t+1
    const int k0 = 2*t, k1 = 2*t + 1;
    const float4 w0 = ((const float4*)hw)[k0];
    const float4 w1 = ((const float4*)hw)[k1];
    const float b0 = hb[k0], b1 = hb[k1];

    // ---- compact pattern enumeration (144 useful patterns on warps 0..4)
    // role 0 (t<81):        full patterns, a_j in {1,2,3}          -> parts 0..3
    // role 1 (w3 l<27):     e123: a0=0, a1..a3 in {1,2,3}          -> accP[0]
    // role 2 (w3 l>=27 / w4 l>=27): e01: a0,a1 in {1,2,3}, a2=a3=0 -> accP[1]/[2]
    // role 3 (w4 l<27):     e012: a3=0, a0..a2 in {1,2,3}          -> accP[3]
    int a0=0, a1=0, a2=0, a3=0, role = -1;
    if (t < 81) {
        role = 0; int f = t;
        a0 = f%3 + 1; f /= 3; a1 = f%3 + 1; f /= 3; a2 = f%3 + 1; a3 = f/3 + 1;
    } else if (t >= 96 && t < 128) {
        const int l = t - 96;
        if (l < 27) { role = 1; int f = l; a1 = f%3+1; f /= 3; a2 = f%3+1; a3 = f/3+1; }
        else        { role = 2; int f = l - 27; a0 = f%3+1; a1 = f/3+1; }       // f 0..4
    } else if (t >= 128 && t < 159) {
        const int l = t - 128;
        if (l < 27) { role = 3; int f = l; a0 = f%3+1; f /= 3; a1 = f%3+1; a2 = f/3+1; }
        else        { role = 2; int f = l - 22; a0 = f%3+1; a1 = f/3+1; }       // f 5..8
    }

    // ---- closed-form Clifford pullback through the 20-CNOT ring (pure ALU).
    const int x0 = (a0 ^ (a0 >> 1)) & 1, z0 = (a0 >> 1) & 1;
    const int x1 = (a1 ^ (a1 >> 1)) & 1, z1 = (a1 >> 1) & 1;
    const int x2 = (a2 ^ (a2 >> 1)) & 1, z2 = (a2 >> 1) & 1;
    const int x3 = (a3 ^ (a3 >> 1)) & 1, z3 = (a3 >> 1) & 1;
    const int p0 =  x0       | ((z1 ^ z2 ^ z3)      << 1);
    const int p1 = (x0 ^ x1) | ((z0 ^ z1 ^ z2 ^ z3) << 1);
    const int p2 = (x1 ^ x2) | ((z0 ^ z2 ^ z3)      << 1);
    const int p3 = (x2 ^ x3) | ((z0 ^ z3)           << 1);
    const int p4 =  x3       | ( z0                 << 1);
    const int S1 = z0 ^ z1 ^ z2 ^ z3, S2 = z0 ^ z2 ^ z3, S3 = z0 ^ z3, S4 = z0;
    const int sign = (x0 & S1 & (1 ^ x1 ^ z0)) ^ (x1 & S2 & (1 ^ x2 ^ z1))
                   ^ (x2 & S3 & (1 ^ x3 ^ z2)) ^ (x3 & S4 & (1 ^ z3));
    const float sgn = 1.f - 2.f * (float)sign;

    __syncthreads();   // barrier 1: M, Nv, gpart ready

    if (warp < 5) {
        // ---- unified observable factor: prod over wires with a_j != 0.
        const int i0 = a0 ? a0-1 : 0, i1 = a1 ? a1-1 : 0,
                  i2 = a2 ? a2-1 : 0, i3 = a3 ? a3-1 : 0;
        const float m0 = a0 ? Nv[0][i0] : 1.f;
        const float m1 = a1 ? Nv[1][i1] : 1.f;
        const float m2 = a2 ? Nv[2][i2] : 1.f;
        const float m3 = a3 ? Nv[3][i3] : 1.f;
        const float nfA = (m0*m1) * (m2*m3);      // valid for roles 0..3
        float nf1 = 0.f, nf2 = 0.f, nf3 = 0.f;
        if (role == 0) {                          // uniform in warps 0-1; predicated in warp 2
            nf1 = (Nv[4][i0]*Nv[5][i1])   * (Nv[6][i2]*Nv[7][i3]);
            nf2 = (Nv[8][i0]*Nv[9][i1])   * (Nv[10][i2]*Nv[11][i3]);
            nf3 = (Nv[12][i0]*Nv[13][i1]) * (Nv[14][i2]*Nv[15][i3]);
        }

        // ---- <psi_qb | P | psi_qb> (packed f32x2, even/odd split)
        float v0, v1, v2, v3;
        {
            const uint32_t mb = (uint32_t)__cvta_generic_to_shared(M);
            const int iz = z0 << 1;
            uint32_t ad[20];
            ad[0] = mb + (0*4 + p0)*16; ad[1] = mb + (1*4 + p1)*16;
            ad[2] = mb + (2*4 + p2)*16; ad[3] = mb + (3*4 + p3)*16;
            ad[4] = mb + (4*4 + p4)*16;
            #pragma unroll
            for (int i = 5; i < 20; ++i) ad[i] = mb + (i*4 + iz)*16;

            unsigned long long aE01, aE23, aO01, aO23;
            lds_v2u64(aE01, aE23, ad[0]);
            lds_v2u64(aO01, aO23, ad[1]);
            #pragma unroll
            for (int i = 2; i < 20; i += 2) {
                unsigned long long lo, hi;
                lds_v2u64(lo, hi, ad[i]);
                mul2(aE01, lo); mul2(aE23, hi);
                lds_v2u64(lo, hi, ad[i+1]);
                mul2(aO01, lo); mul2(aO23, hi);
            }
            mul2(aE01, aO01); mul2(aE23, aO23);
            unpackf2(v0, v1, aE01);
            unpackf2(v2, v3, aE23);
            v0 *= sgn; v1 *= sgn; v2 *= sgn; v3 *= sgn;
        }

        if (warp < 3) {
            // full patterns: 4 wreds (inactive lanes t=81..95 contribute 0)
            const bool act = (t < 81);
            float r0 = wred(act ? nfA*v0 : 0.f);
            float r1 = wred(act ? nf1*v1 : 0.f);
            float r2 = wred(act ? nf2*v2 : 0.f);
            float r3 = wred(act ? nf3*v3 : 0.f);
            if (lane == 0) {
                accF[0][warp] = r0; accF[1][warp] = r1;
                accF[2][warp] = r2; accF[3][warp] = r3;
            }
        } else if (warp == 3) {
            float r4 = wred(role == 1 ? nfA*v0 : 0.f);   // e123
            float r5 = wred(role == 2 ? nfA*v0 : 0.f);   // e01 (first 5)
            if (lane == 0) { accP[0] = r4; accP[1] = r5; }
        } else { // warp == 4
            float r6 = wred(role == 3 ? nfA*v0 : 0.f);   // e012
            float r5 = wred(role == 2 ? nfA*v0 : 0.f);   // e01 (last 4)
            if (lane == 0) { accP[3] = r6; accP[2] = r5; }
        }
    } else {
        // ---- warps 5..7: Gram combine, 5 components each
        const int base = (warp - 5) * 5;
        #pragma unroll
        for (int c = 0; c < 5; ++c) {
            const int k = base + c;
            float4 p4v = *(const float4*)&gpart[k][lane*4];
            float s = (p4v.x + p4v.y) + (p4v.z + p4v.w);
            s = wred(s);
            if (lane == 0) gsh[k] = s;
        }
    }
    __syncthreads();   // barrier 2: accF, accP, gsh ready

    // ---- final combine (all threads, fixed order)
    const float E0 = (accF[0][0] + accF[0][1]) + accF[0][2];
    const float E1 = (accF[1][0] + accF[1][1]) + accF[1][2];
    const float E2 = (accF[2][0] + accF[2][1]) + accF[2][2];
    const float E3 = (accF[3][0] + accF[3][1]) + accF[3][2];
    const float4 ap = *(const float4*)&accP[0];
    const float q0 = ap.x * (E1*E2) * E3;     // e123 * Efull[1..3]
    const float q1 = ap.y + ap.z;             // e01
    const float q2 = ap.w;                    // e012
    const float q3 = E0;                      // Efull[0]

    // ---- head: y = q @ W^T + b ; norm via Gram (no reduction, no extra barrier)
    const float y0 = b0 + q0*w0.x + q1*w0.y + q2*w0.z + q3*w0.w;
    const float y1 = b1 + q0*w1.x + q1*w1.y + q2*w1.z + q3*w1.w;

    // gsh: [0]=G00 [1]=G01 [2]=G02 [3]=G03 [4]=G11 [5]=G12 [6]=G13
    //      [7]=G22 [8]=G23 [9]=G33 [10]=c0 [11]=c1 [12]=c2 [13]=c3 [14]=bb
    const float n = gsh[14]
        + (gsh[0]*q0*q0 + gsh[4]*q1*q1) + (gsh[7]*q2*q2 + gsh[9]*q3*q3)
        + 2.f*((gsh[1]*q0*q1 + gsh[2]*q0*q2) + (gsh[3]*q0*q3 + gsh[5]*q1*q2)
             + (gsh[6]*q1*q3 + gsh[8]*q2*q3)
             + (gsh[10]*q0 + gsh[11]*q1) + (gsh[12]*q2 + gsh[13]*q3));
    const float r = rsqrtf(fmaxf(n, 1e-24f));
    ((float2*)(out + (size_t)b*512))[t] = make_float2(y0*r, y1*r);
}

extern "C" void kernel_launch(void* const* d_in, const int* in_sizes, int n_in,
                              void* d_out, int out_size)
{
    // Map inputs by unique element counts:
    // x=1536, pos_weights=32, layer_1_weights=60, layer_2_weights=48,
    // head_w=2048, head_b=512
    const float *x = nullptr, *pw = nullptr, *l1 = nullptr,
                *l2 = nullptr, *hw = nullptr, *hb = nullptr;
    for (int i = 0; i < n_in; ++i) {
        const float* p = (const float*)d_in[i];
        switch (in_sizes[i]) {
            case 1536: x  = p; break;
            case 32:   pw = p; break;
            case 60:   l1 = p; break;
            case 48:   l2 = p; break;
            case 2048: hw = p; break;
            case 512:  hb = p; break;
            default: break;
        }
    }
    qie_kernel<<<8, 256>>>(x, pw, l1, l2, hw, hb, (float*)d_out);
}